// round 2
// baseline (speedup 1.0000x reference)
#include <cuda_runtime.h>

#define NN   50000
#define EE   800000
#define INC  256
#define HIDC 128
#define OUTC 64

// ---- scratch (no allocs allowed -> device globals) ----
__device__ float g_deg[NN];
__device__ float g_dinv[NN];
__device__ int   g_cnt[NN];
__device__ int   g_row_start[NN + 1];
__device__ int   g_fill[NN];
__device__ int   g_csr_src[EE];
__device__ float g_h1[NN * HIDC];
__device__ float g_a1[NN * HIDC];
__device__ float g_h2[NN * OUTC];
__device__ int   g_is64;

// ---- detect whether edge_index is int64 or int32 ----
// int64 little-endian with values in [0, 50000): every odd 32-bit word is 0.
// For random int32 indices, 64 consecutive zero odd-words has probability ~0.
__global__ void detect_kernel(const int* __restrict__ p) {
    if (threadIdx.x == 0 && blockIdx.x == 0) {
        int ok = 1;
        for (int i = 0; i < 64; i++) {
            int lo = p[2 * i], hi = p[2 * i + 1];
            if (hi != 0 || (unsigned)lo >= (unsigned)NN) { ok = 0; break; }
        }
        g_is64 = ok;
    }
}

__device__ __forceinline__ int edge_at(const void* e, long long pos, int is64) {
    if (is64) return (int)((const long long*)e)[pos];
    return ((const int*)e)[pos];
}

__global__ void init_kernel() {
    int i = blockIdx.x * blockDim.x + threadIdx.x;
    if (i < NN) { g_deg[i] = 1.0f; g_cnt[i] = 0; }   // 1.0 = self loop
}

__global__ void count_kernel(const void* __restrict__ eidx) {
    int e = blockIdx.x * blockDim.x + threadIdx.x;
    if (e < EE) {
        int is64 = g_is64;
        int d = edge_at(eidx, (long long)EE + e, is64);  // row 1 = dst
        atomicAdd(&g_deg[d], 1.0f);
        atomicAdd(&g_cnt[d], 1);
    }
}

__global__ void dinv_kernel() {
    int i = blockIdx.x * blockDim.x + threadIdx.x;
    if (i < NN) g_dinv[i] = rsqrtf(g_deg[i]);
}

// single-block exclusive scan of g_cnt -> g_row_start, also primes g_fill
__global__ void scan_kernel() {
    __shared__ int part[1024];
    int tid = threadIdx.x;
    const int CH = (NN + 1023) / 1024;  // 49
    int base = tid * CH;
    int s = 0;
    for (int j = 0; j < CH; j++) { int i = base + j; if (i < NN) s += g_cnt[i]; }
    part[tid] = s;
    __syncthreads();
    for (int off = 1; off < 1024; off <<= 1) {
        int v = (tid >= off) ? part[tid - off] : 0;
        __syncthreads();
        part[tid] += v;
        __syncthreads();
    }
    int run = (tid == 0) ? 0 : part[tid - 1];
    for (int j = 0; j < CH; j++) {
        int i = base + j;
        if (i < NN) { g_row_start[i] = run; g_fill[i] = run; run += g_cnt[i]; }
    }
    if (tid == 0) g_row_start[NN] = EE;
}

__global__ void fill_kernel(const void* __restrict__ eidx) {
    int e = blockIdx.x * blockDim.x + threadIdx.x;
    if (e < EE) {
        int is64 = g_is64;
        int s = edge_at(eidx, (long long)e, is64);        // row 0 = src
        int d = edge_at(eidx, (long long)EE + e, is64);   // row 1 = dst
        int pos = atomicAdd(&g_fill[d], 1);
        g_csr_src[pos] = s;
    }
}

// ---- tiled fp32 GEMM: C[M,NC] = A[M,KC] @ B[KC,NC] ----
template <int KC, int NC>
__global__ void __launch_bounds__(256) gemm_kernel(
    const float* __restrict__ A, const float* __restrict__ B,
    float* __restrict__ C, int M)
{
    constexpr int TM = 64, TK = 16;
    constexpr int CG = NC / 4;         // col groups (threads along N)
    constexpr int RG = 256 / CG;       // row groups
    constexpr int RPT = TM / RG;       // rows per thread (8 for NC=128, 4 for NC=64)

    __shared__ float As[TK][TM + 4];   // transposed A tile, padded
    __shared__ float Bs[TK][NC];

    int tid  = threadIdx.x;
    int tx   = tid % CG;
    int ty   = tid / CG;
    int row0 = ty * RPT;               // multiple of 4 -> float4-aligned smem reads
    int col  = tx * 4;
    int bm   = blockIdx.x * TM;

    float acc[RPT][4];
    #pragma unroll
    for (int r = 0; r < RPT; r++)
        { acc[r][0] = 0.f; acc[r][1] = 0.f; acc[r][2] = 0.f; acc[r][3] = 0.f; }

    int am  = tid >> 2;                // 0..63 : A row within tile
    int akq = tid & 3;                 // which float4 of 16 K-cols

    for (int k0 = 0; k0 < KC; k0 += TK) {
        // load A tile (guard M boundary)
        float4 av = make_float4(0.f, 0.f, 0.f, 0.f);
        if (bm + am < M)
            av = *(const float4*)(A + (size_t)(bm + am) * KC + k0 + akq * 4);
        As[akq * 4 + 0][am] = av.x;
        As[akq * 4 + 1][am] = av.y;
        As[akq * 4 + 2][am] = av.z;
        As[akq * 4 + 3][am] = av.w;

        // load B tile
        constexpr int BV = (TK * NC / 4) / 256;  // 2 for NC=128, 1 for NC=64
        #pragma unroll
        for (int i = 0; i < BV; i++) {
            int idx = tid + i * 256;
            int bk = idx / CG;
            int bc = (idx % CG) * 4;
            *(float4*)&Bs[bk][bc] = *(const float4*)(B + (size_t)(k0 + bk) * NC + bc);
        }
        __syncthreads();

        #pragma unroll
        for (int k = 0; k < TK; k++) {
            float4 bv = *(const float4*)&Bs[k][col];
            float a[RPT];
            const float4* ap = (const float4*)&As[k][row0];
            #pragma unroll
            for (int q = 0; q < RPT / 4; q++) {
                float4 a4 = ap[q];
                a[q * 4 + 0] = a4.x; a[q * 4 + 1] = a4.y;
                a[q * 4 + 2] = a4.z; a[q * 4 + 3] = a4.w;
            }
            #pragma unroll
            for (int r = 0; r < RPT; r++) {
                acc[r][0] += a[r] * bv.x;
                acc[r][1] += a[r] * bv.y;
                acc[r][2] += a[r] * bv.z;
                acc[r][3] += a[r] * bv.w;
            }
        }
        __syncthreads();
    }

    #pragma unroll
    for (int r = 0; r < RPT; r++) {
        int m = bm + row0 + r;
        if (m < M) {
            *(float4*)(C + (size_t)m * NC + col) =
                make_float4(acc[r][0], acc[r][1], acc[r][2], acc[r][3]);
        }
    }
}

// ---- CSR aggregation: one warp per destination node, atomic-free ----
// out[d] = sum_{e: dst=e->d} h[src_e] * dinv[src]*dinv[d]  + h[d]*dinv[d]^2  + bias
template <int C, bool RELU>
__global__ void __launch_bounds__(256) agg_kernel(
    const float* __restrict__ hin, const float* __restrict__ bias,
    float* __restrict__ out)
{
    int gw   = (blockIdx.x * blockDim.x + threadIdx.x) >> 5;
    int lane = threadIdx.x & 31;
    if (gw >= NN) return;
    constexpr int V = C / 32;          // 4 (C=128) or 2 (C=64)

    float dv = g_dinv[gw];
    float acc[V];
    {   // self loop
        float w = dv * dv;
        const float* hr = hin + (size_t)gw * C + lane * V;
        if constexpr (V == 4) {
            float4 v = *(const float4*)hr;
            acc[0] = v.x * w; acc[1] = v.y * w; acc[2] = v.z * w; acc[3] = v.w * w;
        } else {
            float2 v = *(const float2*)hr;
            acc[0] = v.x * w; acc[1] = v.y * w;
        }
    }

    int beg = g_row_start[gw], end = g_row_start[gw + 1];
    for (int e = beg; e < end; e++) {
        int s = g_csr_src[e];
        float w = dv * g_dinv[s];
        const float* hs = hin + (size_t)s * C + lane * V;
        if constexpr (V == 4) {
            float4 v = *(const float4*)hs;
            acc[0] += v.x * w; acc[1] += v.y * w; acc[2] += v.z * w; acc[3] += v.w * w;
        } else {
            float2 v = *(const float2*)hs;
            acc[0] += v.x * w; acc[1] += v.y * w;
        }
    }

    const float* bp = bias + lane * V;
    float* op = out + (size_t)gw * C + lane * V;
    if constexpr (V == 4) {
        float4 b = *(const float4*)bp;
        float4 o = make_float4(acc[0] + b.x, acc[1] + b.y, acc[2] + b.z, acc[3] + b.w);
        if (RELU) {
            o.x = fmaxf(o.x, 0.f); o.y = fmaxf(o.y, 0.f);
            o.z = fmaxf(o.z, 0.f); o.w = fmaxf(o.w, 0.f);
        }
        *(float4*)op = o;
    } else {
        float2 b = *(const float2*)bp;
        float2 o = make_float2(acc[0] + b.x, acc[1] + b.y);
        if (RELU) { o.x = fmaxf(o.x, 0.f); o.y = fmaxf(o.y, 0.f); }
        *(float2*)op = o;
    }
}

extern "C" void kernel_launch(void* const* d_in, const int* in_sizes, int n_in,
                              void* d_out, int out_size)
{
    const float* x  = (const float*)d_in[0];
    const void*  ei = d_in[1];
    const float* W1 = (const float*)d_in[2];
    const float* b1 = (const float*)d_in[3];
    const float* W2 = (const float*)d_in[4];
    const float* b2 = (const float*)d_in[5];
    float* out = (float*)d_out;

    float *h1, *a1, *h2;
    cudaGetSymbolAddress((void**)&h1, g_h1);
    cudaGetSymbolAddress((void**)&a1, g_a1);
    cudaGetSymbolAddress((void**)&h2, g_h2);

    const int NB = (NN + 255) / 256;
    const int EB = (EE + 255) / 256;

    detect_kernel<<<1, 32>>>((const int*)ei);
    init_kernel<<<NB, 256>>>();
    count_kernel<<<EB, 256>>>(ei);
    dinv_kernel<<<NB, 256>>>();
    scan_kernel<<<1, 1024>>>();
    fill_kernel<<<EB, 256>>>(ei);

    // layer 1: h1 = x @ W1 ; a1 = relu(agg(h1) + b1)
    gemm_kernel<INC, HIDC><<<(NN + 63) / 64, 256>>>(x, W1, h1, NN);
    agg_kernel<HIDC, true><<<(NN * 32 + 255) / 256, 256>>>(h1, b1, a1);

    // layer 2: h2 = a1 @ W2 ; out = agg(h2) + b2
    gemm_kernel<HIDC, OUTC><<<(NN + 63) / 64, 256>>>(a1, W2, h2, NN);
    agg_kernel<OUTC, false><<<(NN * 32 + 255) / 256, 256>>>(h2, b2, out);
}